// round 2
// baseline (speedup 1.0000x reference)
#include <cuda_runtime.h>
#include <cstdint>
#include <math.h>

#define D_MODEL 1024
#define HIDDEN  128
#define MAX_M   16384

// Scratch (static device arrays — no allocation APIs anywhere).
__device__ float g_y1[MAX_M * HIDDEN];             // layer-1 output   (8 MB)
__device__ float g_w1[D_MODEL * 7 * HIDDEN];       // packed W layer 1 (3.7 MB)
__device__ float g_w2[HIDDEN * 7 * D_MODEL];       // packed W layer 2 (3.7 MB)

// ---------------------------------------------------------------------------
// cp.async helpers (sm_103a: LDGSTS path, no register round-trip)
// ---------------------------------------------------------------------------
__device__ __forceinline__ void cp_async16(void* smem_dst, const void* gmem_src) {
    uint32_t d = (uint32_t)__cvta_generic_to_shared(smem_dst);
    asm volatile("cp.async.cg.shared.global [%0], [%1], 16;\n" :: "r"(d), "l"(gmem_src));
}
__device__ __forceinline__ void cp_commit() {
    asm volatile("cp.async.commit_group;\n" ::);
}
__device__ __forceinline__ void cp_wait_all() {
    asm volatile("cp.async.wait_group 0;\n" ::);
}

// ---------------------------------------------------------------------------
// Pack weights into (i, f, o) layout: f=0 -> scale_base, f=1..6 -> coef[g]*scale_sp
// ---------------------------------------------------------------------------
__global__ void pack_w_kernel(const float* __restrict__ coef,
                              const float* __restrict__ sbase,
                              const float* __restrict__ ssp,
                              float* __restrict__ Wout,
                              int IN, int OUT) {
    int idx = blockIdx.x * blockDim.x + threadIdx.x;
    if (idx >= IN * OUT) return;
    int i = idx / OUT;
    int o = idx - i * OUT;
    float sp = ssp[idx];
    Wout[(size_t)(i * 7) * OUT + o] = sbase[idx];
#pragma unroll
    for (int g = 0; g < 6; g++)
        Wout[(size_t)(i * 7 + 1 + g) * OUT + o] = coef[(size_t)idx * 6 + g] * sp;
}

// ---------------------------------------------------------------------------
// 7 features of one scalar: silu(x) and the 6 cubic B-spline basis values on
// the uniform grid knots t_j = -3 + j*(2/3), j=0..9.  For x in knot interval m
// (m = floor((x+3)*1.5), valid 0..8) the 4 nonzero basis funcs j=m-3..m take
// the standard uniform local cubic values; everything else (incl. x outside
// [-3,3)) is exactly 0, matching the reference Cox-de-Boor recursion.
// ---------------------------------------------------------------------------
__device__ __forceinline__ void kan_features(float x, float f[7]) {
    float e = __expf(-x);
    f[0] = x / (1.0f + e);                       // silu
    float t  = (x + 3.0f) * 1.5f;
    float mf = floorf(t);
    int   m  = (int)mf;
    float u  = t - mf;
    float u2 = u * u;
    float u3 = u2 * u;
    float om = 1.0f - u;
    float v0 = om * om * om * (1.0f / 6.0f);                            // j = m-3
    float v1 = (3.0f * u3 - 6.0f * u2 + 4.0f) * (1.0f / 6.0f);          // j = m-2
    float v2 = (-3.0f * u3 + 3.0f * u2 + 3.0f * u + 1.0f) * (1.0f/6.0f);// j = m-1
    float v3 = u3 * (1.0f / 6.0f);                                      // j = m
#pragma unroll
    for (int g = 0; g < 6; g++) f[1 + g] = 0.0f;
    float v[4] = {v0, v1, v2, v3};
#pragma unroll
    for (int k = 0; k < 4; k++) {
        int j = m - 3 + k;
        if (j >= 0 && j < 6) f[1 + j] = v[k];
    }
}

// ---------------------------------------------------------------------------
// Fused feature-expansion + GEMM, double-buffered cp.async pipeline:
//   Y[M, OUT_DIM] = Feat(A)[M, IN_DIM*7] @ W[IN_DIM*7, OUT_DIM]
// Block tile 32 rows x 128 cols, 128 threads, 4x8 micro-tile,
// K-chunks of 8 inputs (56 K values). One __syncthreads per chunk.
// ---------------------------------------------------------------------------
template <int IN_DIM, int OUT_DIM>
__global__ __launch_bounds__(128)
void kan_layer_kernel(const float* __restrict__ A,
                      const float* __restrict__ W,
                      float* __restrict__ Y, int M) {
    constexpr int BM = 32, BN = 128, CI = 8, KC = CI * 7, BMP = 36;

    extern __shared__ float smem[];
    // layout: sF[2][KC][BMP] then sW[2][KC][BN]
    float* sFbase = smem;                       // 2*56*36 floats
    float* sWbase = smem + 2 * KC * BMP;        // 2*56*128 floats

    const int tid     = threadIdx.x;
    const int colg    = tid & 15;   // 0..15 -> cols colg*4..+3 and +64
    const int rowg    = tid >> 4;   // 0..7  -> rows rowg*4..+3
    const int rowBase = blockIdx.x * BM;
    const int colBase = blockIdx.y * BN;

    // per-chunk loader pieces ------------------------------------------------
    // weights: 56x128 tile = 1792 float4, 14 per thread, via cp.async
    auto issue_w = [&](int i0, int p) {
        float* dstbuf = sWbase + p * (KC * BN);
        const float* srcbase = W + (size_t)(i0 * 7) * OUT_DIM + colBase;
#pragma unroll
        for (int l = 0; l < 14; l++) {
            int idx = tid + l * 128;        // 0..1791
            int kk  = idx >> 5;             // / (BN/4)
            int o4  = idx & 31;
            cp_async16(dstbuf + kk * BN + o4 * 4,
                       srcbase + (size_t)kk * OUT_DIM + o4 * 4);
        }
        cp_commit();
    };
    // x values: 32 rows x 8 inputs, 2 per thread
    auto load_x = [&](int i0, float xv[2]) {
#pragma unroll
        for (int e2 = 0; e2 < 2; e2++) {
            int e = tid + e2 * 128;
            int r = e >> 3, c = e & 7;
            int row = rowBase + r;
            xv[e2] = (row < M) ? A[(size_t)row * IN_DIM + i0 + c] : 0.0f;
        }
    };
    auto store_f = [&](const float xv[2], int p) {
        float* dstbuf = sFbase + p * (KC * BMP);
#pragma unroll
        for (int e2 = 0; e2 < 2; e2++) {
            int e = tid + e2 * 128;
            int r = e >> 3, c = e & 7;
            float feat[7];
            kan_features(xv[e2], feat);
#pragma unroll
            for (int f7 = 0; f7 < 7; f7++)
                dstbuf[(c * 7 + f7) * BMP + r] = feat[f7];
        }
    };

    float acc[4][8];
#pragma unroll
    for (int a = 0; a < 4; a++)
#pragma unroll
        for (int b = 0; b < 8; b++) acc[a][b] = 0.0f;

    // prologue: stage chunk 0 into buffer 0
    {
        issue_w(0, 0);
        float xv[2];
        load_x(0, xv);
        store_f(xv, 0);
        cp_wait_all();
        __syncthreads();
    }

    int p = 0;
    for (int i0 = 0; i0 < IN_DIM; i0 += CI) {
        const int nxt = i0 + CI;
        float xv[2];
        if (nxt < IN_DIM) {
            issue_w(nxt, p ^ 1);       // async: overlaps with compute below
            load_x(nxt, xv);           // LDG in flight during compute
        }

        // --- 56 x (4x8) FMA micro-kernel on buffer p ---
        const float* fbuf = sFbase + p * (KC * BMP);
        const float* wbuf = sWbase + p * (KC * BN);
#pragma unroll 8
        for (int kk = 0; kk < KC; kk++) {
            float4 fv = *reinterpret_cast<const float4*>(fbuf + kk * BMP + rowg * 4);
            float4 w0 = *reinterpret_cast<const float4*>(wbuf + kk * BN + colg * 4);
            float4 w1 = *reinterpret_cast<const float4*>(wbuf + kk * BN + colg * 4 + 64);
            float fa[4] = {fv.x, fv.y, fv.z, fv.w};
            float wa[8] = {w0.x, w0.y, w0.z, w0.w, w1.x, w1.y, w1.z, w1.w};
#pragma unroll
            for (int a = 0; a < 4; a++)
#pragma unroll
                for (int b = 0; b < 8; b++)
                    acc[a][b] = fmaf(fa[a], wa[b], acc[a][b]);
        }

        if (nxt < IN_DIM) store_f(xv, p ^ 1);   // features into shadow buffer
        cp_wait_all();
        __syncthreads();
        p ^= 1;
    }

    // --- epilogue ---
#pragma unroll
    for (int a = 0; a < 4; a++) {
        int row = rowBase + rowg * 4 + a;
        if (row < M) {
            float* yr = Y + (size_t)row * OUT_DIM + colBase;
            float4 o0 = {acc[a][0], acc[a][1], acc[a][2], acc[a][3]};
            float4 o1 = {acc[a][4], acc[a][5], acc[a][6], acc[a][7]};
            *reinterpret_cast<float4*>(yr + colg * 4)      = o0;
            *reinterpret_cast<float4*>(yr + colg * 4 + 64) = o1;
        }
    }
}

// ---------------------------------------------------------------------------
extern "C" void kernel_launch(void* const* d_in, const int* in_sizes, int n_in,
                              void* d_out, int out_size) {
    const float* x   = (const float*)d_in[0];
    const float* c1  = (const float*)d_in[1];
    const float* sb1 = (const float*)d_in[2];
    const float* sp1 = (const float*)d_in[3];
    const float* c2  = (const float*)d_in[4];
    const float* sb2 = (const float*)d_in[5];
    const float* sp2 = (const float*)d_in[6];
    float* out = (float*)d_out;

    const int M = in_sizes[0] / D_MODEL;   // 16384 for the bench shape

    float *w1, *w2, *y1;
    cudaGetSymbolAddress((void**)&w1, g_w1);
    cudaGetSymbolAddress((void**)&w2, g_w2);
    cudaGetSymbolAddress((void**)&y1, g_y1);

    constexpr int KC = 56, BMP = 36, BN = 128;
    constexpr int SMEM_BYTES = (2 * KC * BMP + 2 * KC * BN) * 4;  // 73472

    static bool attr_done = false;
    if (!attr_done) {
        cudaFuncSetAttribute(kan_layer_kernel<D_MODEL, HIDDEN>,
                             cudaFuncAttributeMaxDynamicSharedMemorySize, SMEM_BYTES);
        cudaFuncSetAttribute(kan_layer_kernel<HIDDEN, D_MODEL>,
                             cudaFuncAttributeMaxDynamicSharedMemorySize, SMEM_BYTES);
        attr_done = true;
    }

    // Pack weights (cheap, graph-capturable, deterministic every launch).
    {
        int tot = D_MODEL * HIDDEN;
        pack_w_kernel<<<(tot + 255) / 256, 256>>>(c1, sb1, sp1, w1, D_MODEL, HIDDEN);
        pack_w_kernel<<<(tot + 255) / 256, 256>>>(c2, sb2, sp2, w2, HIDDEN, D_MODEL);
    }

    dim3 grid1((M + 31) / 32, HIDDEN / 128);   // 512 x 1
    kan_layer_kernel<D_MODEL, HIDDEN><<<grid1, 128, SMEM_BYTES>>>(x, w1, y1, M);

    dim3 grid2((M + 31) / 32, D_MODEL / 128);  // 512 x 8
    kan_layer_kernel<HIDDEN, D_MODEL><<<grid2, 128, SMEM_BYTES>>>(y1, w2, out, M);
}

// round 17
// speedup vs baseline: 1.1500x; 1.1500x over previous
#include <cuda_runtime.h>
#include <cstdint>
#include <math.h>

#define D_MODEL 1024
#define HIDDEN  128
#define MAX_M   16384

// Scratch (static device arrays — no allocation APIs anywhere).
__device__ float g_y1[MAX_M * HIDDEN];             // layer-1 output   (8 MB)
__device__ float g_w1[D_MODEL * 7 * HIDDEN];       // packed W layer 1 (3.7 MB)
__device__ float g_w2[HIDDEN * 7 * D_MODEL];       // packed W layer 2 (3.7 MB)

// ---------------------------------------------------------------------------
// cp.async helpers (sm_103a: LDGSTS path, no register round-trip)
// ---------------------------------------------------------------------------
__device__ __forceinline__ void cp_async16(void* smem_dst, const void* gmem_src) {
    uint32_t d = (uint32_t)__cvta_generic_to_shared(smem_dst);
    asm volatile("cp.async.cg.shared.global [%0], [%1], 16;\n" :: "r"(d), "l"(gmem_src));
}
__device__ __forceinline__ void cp_commit() {
    asm volatile("cp.async.commit_group;\n" ::);
}
__device__ __forceinline__ void cp_wait_all() {
    asm volatile("cp.async.wait_group 0;\n" ::);
}

// ---------------------------------------------------------------------------
// Pack weights into (i, f, o) layout: f=0 -> scale_base, f=1..6 -> coef[g]*scale_sp
// ---------------------------------------------------------------------------
__global__ void pack_w_kernel(const float* __restrict__ coef,
                              const float* __restrict__ sbase,
                              const float* __restrict__ ssp,
                              float* __restrict__ Wout,
                              int IN, int OUT) {
    int idx = blockIdx.x * blockDim.x + threadIdx.x;
    if (idx >= IN * OUT) return;
    int i = idx / OUT;
    int o = idx - i * OUT;
    float sp = ssp[idx];
    Wout[(size_t)(i * 7) * OUT + o] = sbase[idx];
#pragma unroll
    for (int g = 0; g < 6; g++)
        Wout[(size_t)(i * 7 + 1 + g) * OUT + o] = coef[(size_t)idx * 6 + g] * sp;
}

// ---------------------------------------------------------------------------
// 7 features of one scalar: silu(x) and the 6 cubic B-spline basis values on
// the uniform grid knots t_j = -3 + j*(2/3), j=0..9.  For x in knot interval m
// (m = floor((x+3)*1.5), valid 0..8) the 4 nonzero basis funcs j=m-3..m take
// the standard uniform local cubic values; everything else (incl. x outside
// [-3,3)) is exactly 0, matching the reference Cox-de-Boor recursion.
// ---------------------------------------------------------------------------
__device__ __forceinline__ void kan_features(float x, float f[7]) {
    float e = __expf(-x);
    f[0] = x / (1.0f + e);                       // silu
    float t  = (x + 3.0f) * 1.5f;
    float mf = floorf(t);
    int   m  = (int)mf;
    float u  = t - mf;
    float u2 = u * u;
    float u3 = u2 * u;
    float om = 1.0f - u;
    float v0 = om * om * om * (1.0f / 6.0f);                            // j = m-3
    float v1 = (3.0f * u3 - 6.0f * u2 + 4.0f) * (1.0f / 6.0f);          // j = m-2
    float v2 = (-3.0f * u3 + 3.0f * u2 + 3.0f * u + 1.0f) * (1.0f/6.0f);// j = m-1
    float v3 = u3 * (1.0f / 6.0f);                                      // j = m
#pragma unroll
    for (int g = 0; g < 6; g++) f[1 + g] = 0.0f;
    float v[4] = {v0, v1, v2, v3};
#pragma unroll
    for (int k = 0; k < 4; k++) {
        int j = m - 3 + k;
        if (j >= 0 && j < 6) f[1 + j] = v[k];
    }
}

// ---------------------------------------------------------------------------
// Fused feature-expansion + GEMM, double-buffered cp.async pipeline:
//   Y[M, OUT_DIM] = Feat(A)[M, IN_DIM*7] @ W[IN_DIM*7, OUT_DIM]
// Block tile 64 rows x 128 cols, 128 threads, 8x8 micro-tile in SPLIT-SLICE
// layout: each thread owns rows {rowg*4..+3, 32+rowg*4..+3} and cols
// {colg*4..+3, 64+colg*4..+3}. All four LDS.128 in the inner step are
// 256B-contiguous (weights, 2 phases) or half-warp broadcast (features,
// 1 phase): 6 crossbar phases per 64 FFMA -> FMA-pipe-limited, not smem.
// K-chunks of 8 inputs (56 K values). One __syncthreads per chunk.
// ---------------------------------------------------------------------------
template <int IN_DIM, int OUT_DIM>
__global__ __launch_bounds__(128)
void kan_layer_kernel(const float* __restrict__ A,
                      const float* __restrict__ W,
                      float* __restrict__ Y, int M) {
    constexpr int BM = 64, BN = 128, CI = 8, KC = CI * 7, BMP = 68;

    extern __shared__ float smem[];
    // layout: sF[2][KC][BMP] then sW[2][KC][BN]
    float* sFbase = smem;                       // 2*56*68 floats
    float* sWbase = smem + 2 * KC * BMP;        // 2*56*128 floats

    const int tid     = threadIdx.x;
    const int colg    = tid & 15;   // cols colg*4..+3 and colg*4+64..+67
    const int rowg    = tid >> 4;   // rows rowg*4..+3 and rowg*4+32..+35
    const int rowBase = blockIdx.x * BM;
    const int colBase = blockIdx.y * BN;

    // per-chunk loader pieces ------------------------------------------------
    // weights: 56x128 tile = 1792 float4, 14 per thread, via cp.async
    auto issue_w = [&](int i0, int p) {
        float* dstbuf = sWbase + p * (KC * BN);
        const float* srcbase = W + (size_t)(i0 * 7) * OUT_DIM + colBase;
#pragma unroll
        for (int l = 0; l < 14; l++) {
            int idx = tid + l * 128;        // 0..1791
            int kk  = idx >> 5;             // / (BN/4)
            int o4  = idx & 31;
            cp_async16(dstbuf + kk * BN + o4 * 4,
                       srcbase + (size_t)kk * OUT_DIM + o4 * 4);
        }
        cp_commit();
    };
    // x values: 64 rows x 8 inputs, 4 per thread
    auto load_x = [&](int i0, float xv[4]) {
#pragma unroll
        for (int e2 = 0; e2 < 4; e2++) {
            int e = tid + e2 * 128;
            int r = e >> 3, c = e & 7;
            int row = rowBase + r;
            xv[e2] = (row < M) ? A[(size_t)row * IN_DIM + i0 + c] : 0.0f;
        }
    };
    auto store_f = [&](const float xv[4], int p) {
        float* dstbuf = sFbase + p * (KC * BMP);
#pragma unroll
        for (int e2 = 0; e2 < 4; e2++) {
            int e = tid + e2 * 128;
            int r = e >> 3, c = e & 7;
            float feat[7];
            kan_features(xv[e2], feat);
#pragma unroll
            for (int f7 = 0; f7 < 7; f7++)
                dstbuf[(c * 7 + f7) * BMP + r] = feat[f7];
        }
    };

    float acc[8][8];
#pragma unroll
    for (int a = 0; a < 8; a++)
#pragma unroll
        for (int b = 0; b < 8; b++) acc[a][b] = 0.0f;

    // prologue: stage chunk 0 into buffer 0
    {
        issue_w(0, 0);
        float xv[4];
        load_x(0, xv);
        store_f(xv, 0);
        cp_wait_all();
        __syncthreads();
    }

    int p = 0;
    for (int i0 = 0; i0 < IN_DIM; i0 += CI) {
        const int nxt = i0 + CI;
        float xv[4];
        if (nxt < IN_DIM) {
            issue_w(nxt, p ^ 1);       // async: overlaps with compute below
            load_x(nxt, xv);           // LDG in flight during compute
        }

        // --- 56 x (8x8) FMA micro-kernel on buffer p (split-slice) ---
        const float* fbuf = sFbase + p * (KC * BMP);
        const float* wbuf = sWbase + p * (KC * BN);
#pragma unroll 4
        for (int kk = 0; kk < KC; kk++) {
            float4 f0 = *reinterpret_cast<const float4*>(fbuf + kk * BMP + rowg * 4);
            float4 f1 = *reinterpret_cast<const float4*>(fbuf + kk * BMP + rowg * 4 + 32);
            float4 w0 = *reinterpret_cast<const float4*>(wbuf + kk * BN + colg * 4);
            float4 w1 = *reinterpret_cast<const float4*>(wbuf + kk * BN + colg * 4 + 64);
            float fa[8] = {f0.x, f0.y, f0.z, f0.w, f1.x, f1.y, f1.z, f1.w};
            float wa[8] = {w0.x, w0.y, w0.z, w0.w, w1.x, w1.y, w1.z, w1.w};
#pragma unroll
            for (int a = 0; a < 8; a++)
#pragma unroll
                for (int b = 0; b < 8; b++)
                    acc[a][b] = fmaf(fa[a], wa[b], acc[a][b]);
        }

        if (nxt < IN_DIM) store_f(xv, p ^ 1);   // features into shadow buffer
        cp_wait_all();
        __syncthreads();
        p ^= 1;
    }

    // --- epilogue: split-slice rows/cols per thread ---
#pragma unroll
    for (int a = 0; a < 8; a++) {
        int rloc = (a < 4) ? (rowg * 4 + a) : (32 + rowg * 4 + (a - 4));
        int row  = rowBase + rloc;
        if (row < M) {
            float* yr = Y + (size_t)row * OUT_DIM + colBase;
            float4 o0 = {acc[a][0], acc[a][1], acc[a][2], acc[a][3]};
            float4 o1 = {acc[a][4], acc[a][5], acc[a][6], acc[a][7]};
            *reinterpret_cast<float4*>(yr + colg * 4)      = o0;
            *reinterpret_cast<float4*>(yr + colg * 4 + 64) = o1;
        }
    }
}

// ---------------------------------------------------------------------------
extern "C" void kernel_launch(void* const* d_in, const int* in_sizes, int n_in,
                              void* d_out, int out_size) {
    const float* x   = (const float*)d_in[0];
    const float* c1  = (const float*)d_in[1];
    const float* sb1 = (const float*)d_in[2];
    const float* sp1 = (const float*)d_in[3];
    const float* c2  = (const float*)d_in[4];
    const float* sb2 = (const float*)d_in[5];
    const float* sp2 = (const float*)d_in[6];
    float* out = (float*)d_out;

    const int M = in_sizes[0] / D_MODEL;   // 16384 for the bench shape

    float *w1, *w2, *y1;
    cudaGetSymbolAddress((void**)&w1, g_w1);
    cudaGetSymbolAddress((void**)&w2, g_w2);
    cudaGetSymbolAddress((void**)&y1, g_y1);

    constexpr int KC = 56, BMP = 68, BN = 128;
    constexpr int SMEM_BYTES = (2 * KC * BMP + 2 * KC * BN) * 4;  // 87808

    // Unconditional (deterministic, no static guards per harness contract).
    cudaFuncSetAttribute(kan_layer_kernel<D_MODEL, HIDDEN>,
                         cudaFuncAttributeMaxDynamicSharedMemorySize, SMEM_BYTES);
    cudaFuncSetAttribute(kan_layer_kernel<HIDDEN, D_MODEL>,
                         cudaFuncAttributeMaxDynamicSharedMemorySize, SMEM_BYTES);

    // Pack weights (cheap, graph-capturable, deterministic every launch).
    {
        int tot = D_MODEL * HIDDEN;
        pack_w_kernel<<<(tot + 255) / 256, 256>>>(c1, sb1, sp1, w1, D_MODEL, HIDDEN);
        pack_w_kernel<<<(tot + 255) / 256, 256>>>(c2, sb2, sp2, w2, HIDDEN, D_MODEL);
    }

    dim3 grid1((M + 63) / 64, HIDDEN / 128);   // 256 x 1
    kan_layer_kernel<D_MODEL, HIDDEN><<<grid1, 128, SMEM_BYTES>>>(x, w1, y1, M);

    dim3 grid2((M + 63) / 64, D_MODEL / 128);  // 256 x 8
    kan_layer_kernel<HIDDEN, D_MODEL><<<grid2, 128, SMEM_BYTES>>>(y1, w2, out, M);
}